// round 15
// baseline (speedup 1.0000x reference)
#include <cuda_runtime.h>
#include <cuda_fp16.h>
#include <math.h>
#include <stdint.h>

// Problem constants
#define BB 2
#define SS 2048
#define HH 2048
#define NH 16
#define NKV 4
#define HD 128
#define NREP (NH / NKV)
#define M_TOK (BB * SS)
#define SCALE_F 0.08838834764831845f

// ---------------------------------------------------------------------------
// Scratch (fp16 hi-only)
// ---------------------------------------------------------------------------
__device__ __half g_h_h[M_TOK * HH];
__device__ __half g_qw_h[NH * HD * HH];
__device__ __half g_kw_h[NKV * HD * HH];
__device__ __half g_vw_h[NKV * HD * HH];
__device__ __half g_ow_h[HH * NH * HD];
__device__ __half g_qh[M_TOK * NH * HD];
__device__ __half g_kh[M_TOK * NKV * HD];
__device__ __half g_vh[M_TOK * NKV * HD];
__device__ __half g_ao_h[M_TOK * NH * HD];

// ---------------------------------------------------------------------------
// Helpers
// ---------------------------------------------------------------------------
__device__ __forceinline__ uint32_t smem_u32(const void* p) {
    uint32_t a;
    asm("{ .reg .u64 t; cvta.to.shared.u64 t, %1; cvt.u32.u64 %0, t; }"
        : "=r"(a) : "l"(p));
    return a;
}
__device__ __forceinline__ void ldsm_x4(uint32_t* r, uint32_t addr) {
    asm volatile("ldmatrix.sync.aligned.m8n8.x4.shared.b16 {%0,%1,%2,%3}, [%4];"
                 : "=r"(r[0]), "=r"(r[1]), "=r"(r[2]), "=r"(r[3]) : "r"(addr));
}
__device__ __forceinline__ void ldsm_x4_t(uint32_t* r, uint32_t addr) {
    asm volatile("ldmatrix.sync.aligned.m8n8.x4.trans.shared.b16 {%0,%1,%2,%3}, [%4];"
                 : "=r"(r[0]), "=r"(r[1]), "=r"(r[2]), "=r"(r[3]) : "r"(addr));
}
__device__ __forceinline__ void mma_f16(float* c, const uint32_t* a, const uint32_t* b) {
    asm volatile(
        "mma.sync.aligned.m16n8k16.row.col.f32.f16.f16.f32 "
        "{%0,%1,%2,%3}, {%4,%5,%6,%7}, {%8,%9}, {%0,%1,%2,%3};"
        : "+f"(c[0]), "+f"(c[1]), "+f"(c[2]), "+f"(c[3])
        : "r"(a[0]), "r"(a[1]), "r"(a[2]), "r"(a[3]), "r"(b[0]), "r"(b[1]));
}
__device__ __forceinline__ void mma_f16_b2(float* c, const uint32_t* a,
                                           uint32_t b0, uint32_t b1) {
    uint32_t b[2] = {b0, b1};
    mma_f16(c, a, b);
}
__device__ __forceinline__ void cp_async16(uint32_t dst, const void* src) {
    asm volatile("cp.async.cg.shared.global [%0], [%1], 16;"
                 :: "r"(dst), "l"(src));
}
__device__ __forceinline__ void cp_commit() {
    asm volatile("cp.async.commit_group;" ::: "memory");
}
template <int N> __device__ __forceinline__ void cp_wait() {
    asm volatile("cp.async.wait_group %0;" :: "n"(N) : "memory");
}
__device__ __forceinline__ uint32_t pack2h(float a, float b) {
    __half2 t = __floats2half2_rn(a, b);
    return *(uint32_t*)&t;
}

// ---------------------------------------------------------------------------
// Merged fp32 -> fp16 convert for all 5 tensors.
// ---------------------------------------------------------------------------
__global__ void convert_all_kernel(
    const float* __restrict__ hidden, __half* __restrict__ h_h,
    const float* __restrict__ q_w, __half* __restrict__ qw_h,
    const float* __restrict__ k_w, __half* __restrict__ kw_h,
    const float* __restrict__ v_w, __half* __restrict__ vw_h,
    const float* __restrict__ o_w, __half* __restrict__ ow_h)
{
    int blk = blockIdx.x;
    const float* x; __half* y; int base;
    if (blk < 2048)      { x = hidden; y = h_h;  base = blk; }
    else if (blk < 3072) { x = q_w;    y = qw_h; base = blk - 2048; }
    else if (blk < 3328) { x = k_w;    y = kw_h; base = blk - 3072; }
    else if (blk < 3584) { x = v_w;    y = vw_h; base = blk - 3328; }
    else                 { x = o_w;    y = ow_h; base = blk - 3584; }
    long i = ((long)base * 256 + threadIdx.x) << 4;
    float4 a = *(const float4*)(x + i);
    float4 b = *(const float4*)(x + i + 4);
    float4 c = *(const float4*)(x + i + 8);
    float4 d = *(const float4*)(x + i + 12);
    uint4 u0, u1;
    u0.x = pack2h(a.x, a.y); u0.y = pack2h(a.z, a.w);
    u0.z = pack2h(b.x, b.y); u0.w = pack2h(b.z, b.w);
    u1.x = pack2h(c.x, c.y); u1.y = pack2h(c.z, c.w);
    u1.z = pack2h(d.x, d.y); u1.w = pack2h(d.z, d.w);
    *(uint4*)(y + i) = u0;
    *(uint4*)(y + i + 8) = u1;
}

// ---------------------------------------------------------------------------
// Pipelined 1-term fp16 GEMM core. Block tile 128x128, 128 threads (4 warps),
// warp tile 64x64 (2x2 layout). BK=64, 3-stage cp.async, cp_wait<1>,
// ONE __syncthreads per K-tile.
// Stage layout: A [0,18432), B [18432,36864). Stage stride 36864.
// ---------------------------------------------------------------------------
#define SSTR 72
#define MAT_BYTES 18432
#define STG_BYTES 36864
#define NSTG 3
#define GSMEM_BYTES (NSTG * STG_BYTES)   // 110592

struct GemmAcc { float a[4][8][4]; };    // 4 m-frags x 8 n-frags x 4

__device__ __forceinline__ void gemm_stage_load(
    uint32_t sdst, const __half* Ah, const __half* Bh,
    int row0, int col0, int K, int kof, int tid)
{
    // 1024 16B-chunks per matrix, 128 threads -> 8 per thread per matrix
#pragma unroll
    for (int j = 0; j < 8; j++) {
        int i = tid + j * 128;
        int r = i >> 3, c = (i & 7) * 8;
        uint32_t so = (uint32_t)(r * SSTR + c) * 2;
        cp_async16(sdst + so,             Ah + (long)(row0 + r) * K + kof + c);
        cp_async16(sdst + MAT_BYTES + so, Bh + (long)(col0 + r) * K + kof + c);
    }
}

__device__ __forceinline__ void gemm_core(
    char* smem, const __half* Ah, const __half* Bh,
    int row0, int col0, int K, int tid, int wm, int wn, GemmAcc& A)
{
#pragma unroll
    for (int mt = 0; mt < 4; mt++)
#pragma unroll
        for (int nt = 0; nt < 8; nt++)
#pragma unroll
            for (int j = 0; j < 4; j++) A.a[mt][nt][j] = 0.0f;

    const int lane = tid & 31;
    const uint32_t sb = smem_u32(smem);
    const int x4_r = (lane & 7) + ((lane >> 3) & 1) * 8;
    const int x4_c = (lane >> 4) * 8;

    const int niter = K / 64;

    // prologue: fill 2 stages (commit each; uniform group counting)
#pragma unroll
    for (int s = 0; s < NSTG - 1; s++) {
        if (s < niter)
            gemm_stage_load(sb + (uint32_t)s * STG_BYTES, Ah, Bh,
                            row0, col0, K, s * 64, tid);
        cp_commit();
    }

    int stg_cur = 0;
    for (int kt = 0; kt < niter; kt++) {
        cp_wait<1>();      // group kt complete (committed at iter kt-2)
        __syncthreads();   // stage (kt+2)%3 readers (iter kt-1) done

        int stg_nxt = stg_cur + 2;
        if (stg_nxt >= NSTG) stg_nxt -= NSTG;
        if (kt + 2 < niter)
            gemm_stage_load(sb + (uint32_t)stg_nxt * STG_BYTES, Ah, Bh,
                            row0, col0, K, (kt + 2) * 64, tid);
        cp_commit();

        const uint32_t aA = sb + (uint32_t)stg_cur * STG_BYTES;
        const uint32_t aB = aA + MAT_BYTES;
#pragma unroll
        for (int ks = 0; ks < 4; ks++) {
            uint32_t ah[4][4];
#pragma unroll
            for (int mt = 0; mt < 4; mt++) {
                uint32_t off = (uint32_t)((wm + mt * 16 + x4_r) * SSTR + ks * 16 + x4_c) * 2;
                ldsm_x4(ah[mt], aA + off);
            }
#pragma unroll
            for (int nt2 = 0; nt2 < 4; nt2++) {
                uint32_t boff = (uint32_t)((wn + nt2 * 16 + x4_r) * SSTR + ks * 16 + x4_c) * 2;
                uint32_t bb[4];
                ldsm_x4(bb, aB + boff);
#pragma unroll
                for (int mt = 0; mt < 4; mt++) {
                    mma_f16_b2(A.a[mt][2 * nt2],     ah[mt], bb[0], bb[2]);
                    mma_f16_b2(A.a[mt][2 * nt2 + 1], ah[mt], bb[1], bb[3]);
                }
            }
        }
        if (++stg_cur == NSTG) stg_cur = 0;
    }
    // NOTE: no trailing sync — epilogues that reuse smem must sync first.
}

// ---------------------------------------------------------------------------
// Fused QKV projection. grid = (24, 32), 128 threads.
// ---------------------------------------------------------------------------
__global__ __launch_bounds__(128, 2) void qkv_gemm_kernel(
    const __half* __restrict__ Ah,
    const __half* __restrict__ QWh, const __half* __restrict__ KWh,
    const __half* __restrict__ VWh,
    const float* __restrict__ q_b, const float* __restrict__ k_b,
    const float* __restrict__ v_b,
    __half* __restrict__ Qo, __half* __restrict__ Ko, __half* __restrict__ Vo,
    const float* __restrict__ cosp, const float* __restrict__ sinp)
{
    extern __shared__ __align__(16) char smem[];

    const int bx = blockIdx.x;
    const __half* Bh;
    const float* bias;
    __half* Chi;
    int N, col0, mode;
    float scale;
    if (bx < 16) {
        Bh = QWh; bias = q_b; Chi = Qo;
        N = NH * HD; col0 = bx * 128; mode = 1; scale = SCALE_F;
    } else if (bx < 20) {
        Bh = KWh; bias = k_b; Chi = Ko;
        N = NKV * HD; col0 = (bx - 16) * 128; mode = 1; scale = 1.0f;
    } else {
        Bh = VWh; bias = v_b; Chi = Vo;
        N = NKV * HD; col0 = (bx - 20) * 128; mode = 2; scale = 1.0f;
    }

    const int tid  = threadIdx.x;
    const int wid  = tid >> 5;
    const int lane = tid & 31;
    const int wm   = (wid >> 1) * 64;
    const int wn   = (wid & 1) * 64;
    const int row0 = blockIdx.y * 128;

    GemmAcc A;
    gemm_core(smem, Ah, Bh, row0, col0, HH, tid, wm, wn, A);

    if (mode == 2) {
        const int em = row0 + wm + (lane >> 2);
        const int enl = wn + (lane & 3) * 2;
#pragma unroll
        for (int mt = 0; mt < 4; mt++) {
#pragma unroll
            for (int nt = 0; nt < 8; nt++) {
                int n = col0 + enl + nt * 8;
                float b0 = bias[n], b1 = bias[n + 1];
                long o0 = (long)(em + mt * 16) * N + n;
                long o1 = (long)(em + mt * 16 + 8) * N + n;
                *(uint32_t*)&Chi[o0] = pack2h(A.a[mt][nt][0] + b0, A.a[mt][nt][1] + b1);
                *(uint32_t*)&Chi[o1] = pack2h(A.a[mt][nt][2] + b0, A.a[mt][nt][3] + b1);
            }
        }
    } else {
        // bias + RoPE (+scale) via 64-row smem staging (two halves)
        float* buf = (float*)smem;   // 64 x 132 fp32 = 33792 B (< 110592)
        const int r0l = lane >> 2;
        const int c0l = (lane & 3) * 2;
#pragma unroll
        for (int hf = 0; hf < 2; hf++) {
            __syncthreads();   // also covers mainloop exit before smem reuse
            if (wm == hf * 64) {
#pragma unroll
                for (int mt = 0; mt < 4; mt++) {
                    int slot = mt * 16 + r0l;
#pragma unroll
                    for (int nt = 0; nt < 8; nt++) {
                        int cc2 = wn + nt * 8 + c0l;
                        float b0 = bias[col0 + cc2];
                        float b1 = bias[col0 + cc2 + 1];
                        buf[slot * 132 + cc2]           = A.a[mt][nt][0] + b0;
                        buf[slot * 132 + cc2 + 1]       = A.a[mt][nt][1] + b1;
                        buf[(slot + 8) * 132 + cc2]     = A.a[mt][nt][2] + b0;
                        buf[(slot + 8) * 132 + cc2 + 1] = A.a[mt][nt][3] + b1;
                    }
                }
            }
            __syncthreads();
            for (int i = tid; i < 4096; i += 128) {
                int slot = i >> 6, d = i & 63;
                int grow = row0 + hf * 64 + slot;
                float x1 = buf[slot * 132 + d];
                float x2 = buf[slot * 132 + d + 64];
                long cb = (long)grow * HD;
                float c1 = cosp[cb + d],      s1 = sinp[cb + d];
                float c2 = cosp[cb + d + 64], s2 = sinp[cb + d + 64];
                float y1 = (x1 * c1 - x2 * s1) * scale;
                float y2 = (x2 * c2 + x1 * s2) * scale;
                long o1 = (long)grow * N + col0 + d;
                Chi[o1]      = __float2half_rn(y1);
                Chi[o1 + 64] = __float2half_rn(y2);
            }
        }
    }
}

// ---------------------------------------------------------------------------
// Output projection: fp32 out, no bias. grid = (16, 32), 128 threads.
// ---------------------------------------------------------------------------
__global__ __launch_bounds__(128, 2) void o_gemm_kernel(
    const __half* __restrict__ Ah, const __half* __restrict__ Bh,
    float* __restrict__ Cf, int M, int N, int K)
{
    extern __shared__ __align__(16) char smem[];
    const int tid  = threadIdx.x;
    const int wid  = tid >> 5;
    const int lane = tid & 31;
    const int wm   = (wid >> 1) * 64;
    const int wn   = (wid & 1) * 64;
    const int row0 = blockIdx.y * 128;
    const int col0 = blockIdx.x * 128;

    GemmAcc A;
    gemm_core(smem, Ah, Bh, row0, col0, K, tid, wm, wn, A);

    const int em = row0 + wm + (lane >> 2);
    const int en = col0 + wn + (lane & 3) * 2;
#pragma unroll
    for (int mt = 0; mt < 4; mt++) {
#pragma unroll
        for (int nt = 0; nt < 8; nt++) {
            int n = en + nt * 8;
            float2 v0, v1;
            v0.x = A.a[mt][nt][0]; v0.y = A.a[mt][nt][1];
            v1.x = A.a[mt][nt][2]; v1.y = A.a[mt][nt][3];
            *(float2*)&Cf[(long)(em + mt * 16) * N + n] = v0;
            *(float2*)&Cf[(long)(em + mt * 16 + 8) * N + n] = v1;
        }
    }
}

// ---------------------------------------------------------------------------
// FA2-style flash attention (unchanged — R10/R11 WIN config).
// smem map: Q [0,34816) | st0 K [34816,52224) V [52224,69632)
//           | st1 K [69632,87040) V [87040,104448). Stage stride 34816.
// ---------------------------------------------------------------------------
#define FQSTR 136
#define FOQ 0u
#define FOK 34816u
#define FKVB 34816u
#define FOV 52224u
#define FSM_BYTES 104448u

__global__ __launch_bounds__(256) void flash_mma_kernel(
    const __half* __restrict__ Qh, const __half* __restrict__ Kh,
    const __half* __restrict__ Vh, __half* __restrict__ AOh)
{
    extern __shared__ char fsm2[];
    const uint32_t sb = smem_u32(fsm2);
    const uint32_t aQ = sb + FOQ;

    const int it = (int)gridDim.x - 1 - (int)blockIdx.x;
    const int h  = blockIdx.y;
    const int b  = blockIdx.z;
    const int g  = h / NREP;
    const int tid  = threadIdx.x;
    const int wid  = tid >> 5;
    const int lane = tid & 31;
    const int wq   = wid * 16;
    const int i0 = it * 128;
    const int m0 = b * SS + i0;

    for (int i = tid; i < 2048; i += 256) {
        int r = i >> 4, c = (i & 15) * 8;
        long gi = (long)(m0 + r) * (NH * HD) + h * HD + c;
        *(uint4*)(fsm2 + FOQ + (r * FQSTR + c) * 2) = *(const uint4*)&Qh[gi];
    }

    const int ntiles = 2 * it + 2;

    {
        uint32_t kd = sb + FOK, vd = sb + FOV;
        for (int i = tid; i < 1024; i += 256) {
            int r = i >> 4, c = (i & 15) * 8;
            long gi = (long)(b * SS + r) * (NKV * HD) + g * HD + c;
            cp_async16(kd + (r * FQSTR + c) * 2, Kh + gi);
            cp_async16(vd + (r * FQSTR + c) * 2, Vh + gi);
        }
        cp_commit();
    }

    float out[16][4];
#pragma unroll
    for (int nt = 0; nt < 16; nt++)
#pragma unroll
        for (int j = 0; j < 4; j++) out[nt][j] = 0.0f;
    float m0r = -1e30f, m1r = -1e30f, l0 = 0.0f, l1 = 0.0f;

    const int r0    = lane >> 2;
    const int qcol2 = (lane & 3) * 2;
    const int x4_r = (lane & 7) + ((lane >> 3) & 1) * 8;
    const int x4_c = (lane >> 4) * 8;

    for (int jt = 0; jt < ntiles; jt++) {
        const int j0 = jt * 64;
        const uint32_t aK = sb + FOK + (uint32_t)(jt & 1) * FKVB;
        const uint32_t aV = sb + FOV + (uint32_t)(jt & 1) * FKVB;

        cp_wait<0>();
        __syncthreads();

        if (jt + 1 < ntiles) {
            uint32_t kd = sb + FOK + (uint32_t)((jt + 1) & 1) * FKVB;
            uint32_t vd = sb + FOV + (uint32_t)((jt + 1) & 1) * FKVB;
            int jn = (jt + 1) * 64;
            for (int i = tid; i < 1024; i += 256) {
                int r = i >> 4, c = (i & 15) * 8;
                long gi = (long)(b * SS + jn + r) * (NKV * HD) + g * HD + c;
                cp_async16(kd + (r * FQSTR + c) * 2, Kh + gi);
                cp_async16(vd + (r * FQSTR + c) * 2, Vh + gi);
            }
            cp_commit();
        }

        float sc[8][4];
#pragma unroll
        for (int nt = 0; nt < 8; nt++)
#pragma unroll
            for (int j = 0; j < 4; j++) sc[nt][j] = 0.0f;

#pragma unroll
        for (int kg = 0; kg < 8; kg++) {
            uint32_t qh[4];
            ldsm_x4(qh, aQ + (uint32_t)((wq + x4_r) * FQSTR + kg * 16 + x4_c) * 2);
#pragma unroll
            for (int nt2 = 0; nt2 < 4; nt2++) {
                uint32_t kb[4];
                ldsm_x4(kb, aK + (uint32_t)((nt2 * 16 + x4_r) * FQSTR + kg * 16 + x4_c) * 2);
                mma_f16_b2(sc[2 * nt2],     qh, kb[0], kb[2]);
                mma_f16_b2(sc[2 * nt2 + 1], qh, kb[1], kb[3]);
            }
        }

        if (j0 + 63 > i0 + wq) {
#pragma unroll
            for (int nt = 0; nt < 8; nt++) {
                int colb = j0 + nt * 8 + qcol2;
                int rowa = i0 + wq + r0;
#pragma unroll
                for (int j = 0; j < 4; j++) {
                    int col = colb + (j & 1);
                    int row = rowa + (j >= 2 ? 8 : 0);
                    if (col > row) sc[nt][j] = -1e30f;
                }
            }
        }

        float mx0 = -1e30f, mx1 = -1e30f;
#pragma unroll
        for (int nt = 0; nt < 8; nt++) {
            mx0 = fmaxf(mx0, fmaxf(sc[nt][0], sc[nt][1]));
            mx1 = fmaxf(mx1, fmaxf(sc[nt][2], sc[nt][3]));
        }
        mx0 = fmaxf(mx0, __shfl_xor_sync(0xffffffffu, mx0, 1));
        mx0 = fmaxf(mx0, __shfl_xor_sync(0xffffffffu, mx0, 2));
        mx1 = fmaxf(mx1, __shfl_xor_sync(0xffffffffu, mx1, 1));
        mx1 = fmaxf(mx1, __shfl_xor_sync(0xffffffffu, mx1, 2));

        float mn0 = fmaxf(m0r, mx0);
        float mn1 = fmaxf(m1r, mx1);
        float al0 = __expf(m0r - mn0);
        float al1 = __expf(m1r - mn1);
        m0r = mn0; m1r = mn1;

        float s0 = 0.0f, s1 = 0.0f;
#pragma unroll
        for (int nt = 0; nt < 8; nt++) {
            sc[nt][0] = __expf(sc[nt][0] - mn0);
            sc[nt][1] = __expf(sc[nt][1] - mn0);
            sc[nt][2] = __expf(sc[nt][2] - mn1);
            sc[nt][3] = __expf(sc[nt][3] - mn1);
            s0 += sc[nt][0] + sc[nt][1];
            s1 += sc[nt][2] + sc[nt][3];
        }
        s0 += __shfl_xor_sync(0xffffffffu, s0, 1);
        s0 += __shfl_xor_sync(0xffffffffu, s0, 2);
        s1 += __shfl_xor_sync(0xffffffffu, s1, 1);
        s1 += __shfl_xor_sync(0xffffffffu, s1, 2);
        l0 = l0 * al0 + s0;
        l1 = l1 * al1 + s1;

#pragma unroll
        for (int nt = 0; nt < 16; nt++) {
            out[nt][0] *= al0; out[nt][1] *= al0;
            out[nt][2] *= al1; out[nt][3] *= al1;
        }

#pragma unroll
        for (int kg = 0; kg < 4; kg++) {
            uint32_t pa[4];
            pa[0] = pack2h(sc[2 * kg][0],     sc[2 * kg][1]);
            pa[1] = pack2h(sc[2 * kg][2],     sc[2 * kg][3]);
            pa[2] = pack2h(sc[2 * kg + 1][0], sc[2 * kg + 1][1]);
            pa[3] = pack2h(sc[2 * kg + 1][2], sc[2 * kg + 1][3]);
#pragma unroll
            for (int ntp = 0; ntp < 8; ntp++) {
                uint32_t vh4[4];
                ldsm_x4_t(vh4, aV + (uint32_t)((kg * 16 + x4_r) * FQSTR + ntp * 16 + x4_c) * 2);
                mma_f16(out[2 * ntp],     pa, &vh4[0]);
                mma_f16(out[2 * ntp + 1], pa, &vh4[2]);
            }
        }
    }

    float inv0 = 1.0f / l0;
    float inv1 = 1.0f / l1;
#pragma unroll
    for (int nt = 0; nt < 16; nt++) {
        int col = nt * 8 + qcol2;
        long ra = (long)(m0 + wq + r0) * (NH * HD) + h * HD + col;
        long rb = (long)(m0 + wq + r0 + 8) * (NH * HD) + h * HD + col;
        *(uint32_t*)&AOh[ra] = pack2h(out[nt][0] * inv0, out[nt][1] * inv0);
        *(uint32_t*)&AOh[rb] = pack2h(out[nt][2] * inv1, out[nt][3] * inv1);
    }
}

// ---------------------------------------------------------------------------
// Launcher
// ---------------------------------------------------------------------------
extern "C" void kernel_launch(void* const* d_in, const int* in_sizes, int n_in,
                              void* d_out, int out_size)
{
    const float* hidden = (const float*)d_in[0];
    const float* cosp   = (const float*)d_in[1];
    const float* sinp   = (const float*)d_in[2];
    const float* q_w = (const float*)d_in[4];
    const float* q_b = (const float*)d_in[5];
    const float* k_w = (const float*)d_in[6];
    const float* k_b = (const float*)d_in[7];
    const float* v_w = (const float*)d_in[8];
    const float* v_b = (const float*)d_in[9];
    const float* o_w = (const float*)d_in[10];
    float* out = (float*)d_out;

    __half *h_h, *qw_h, *kw_h, *vw_h, *ow_h, *qh, *kh, *vh, *ao_h;
    cudaGetSymbolAddress((void**)&h_h, g_h_h);
    cudaGetSymbolAddress((void**)&qw_h, g_qw_h);
    cudaGetSymbolAddress((void**)&kw_h, g_kw_h);
    cudaGetSymbolAddress((void**)&vw_h, g_vw_h);
    cudaGetSymbolAddress((void**)&ow_h, g_ow_h);
    cudaGetSymbolAddress((void**)&qh, g_qh);
    cudaGetSymbolAddress((void**)&kh, g_kh);
    cudaGetSymbolAddress((void**)&vh, g_vh);
    cudaGetSymbolAddress((void**)&ao_h, g_ao_h);

    // One merged convert launch
    convert_all_kernel<<<4608, 256>>>(hidden, h_h, q_w, qw_h, k_w, kw_h,
                                      v_w, vw_h, o_w, ow_h);

    // Fused QKV projection (128 threads, warp tile 64x64)
    cudaFuncSetAttribute(qkv_gemm_kernel,
                         cudaFuncAttributeMaxDynamicSharedMemorySize, GSMEM_BYTES);
    qkv_gemm_kernel<<<dim3(24, M_TOK / 128), 128, GSMEM_BYTES>>>(
        h_h, qw_h, kw_h, vw_h, q_b, k_b, v_b, qh, kh, vh, cosp, sinp);

    // Flash attention
    cudaFuncSetAttribute(flash_mma_kernel,
                         cudaFuncAttributeMaxDynamicSharedMemorySize, FSM_BYTES);
    flash_mma_kernel<<<dim3(SS / 128, NH, BB), 256, FSM_BYTES>>>(
        qh, kh, vh, ao_h);

    // Output projection (128 threads, warp tile 64x64)
    cudaFuncSetAttribute(o_gemm_kernel,
                         cudaFuncAttributeMaxDynamicSharedMemorySize, GSMEM_BYTES);
    o_gemm_kernel<<<dim3(HH / 128, M_TOK / 128), 128, GSMEM_BYTES>>>(
        ao_h, ow_h, out, M_TOK, HH, NH * HD);
}

// round 16
// speedup vs baseline: 1.0178x; 1.0178x over previous
#include <cuda_runtime.h>
#include <cuda_fp16.h>
#include <math.h>
#include <stdint.h>

// Problem constants
#define BB 2
#define SS 2048
#define HH 2048
#define NH 16
#define NKV 4
#define HD 128
#define NREP (NH / NKV)
#define M_TOK (BB * SS)
#define SCALE_F 0.08838834764831845f
#define NPERSIST 296   // 148 SMs x 2 CTAs

// ---------------------------------------------------------------------------
// Scratch (fp16 hi-only)
// ---------------------------------------------------------------------------
__device__ __half g_h_h[M_TOK * HH];
__device__ __half g_qw_h[NH * HD * HH];
__device__ __half g_kw_h[NKV * HD * HH];
__device__ __half g_vw_h[NKV * HD * HH];
__device__ __half g_ow_h[HH * NH * HD];
__device__ __half g_qh[M_TOK * NH * HD];
__device__ __half g_kh[M_TOK * NKV * HD];
__device__ __half g_vh[M_TOK * NKV * HD];
__device__ __half g_ao_h[M_TOK * NH * HD];

// ---------------------------------------------------------------------------
// Helpers
// ---------------------------------------------------------------------------
__device__ __forceinline__ uint32_t smem_u32(const void* p) {
    uint32_t a;
    asm("{ .reg .u64 t; cvta.to.shared.u64 t, %1; cvt.u32.u64 %0, t; }"
        : "=r"(a) : "l"(p));
    return a;
}
__device__ __forceinline__ void ldsm_x4(uint32_t* r, uint32_t addr) {
    asm volatile("ldmatrix.sync.aligned.m8n8.x4.shared.b16 {%0,%1,%2,%3}, [%4];"
                 : "=r"(r[0]), "=r"(r[1]), "=r"(r[2]), "=r"(r[3]) : "r"(addr));
}
__device__ __forceinline__ void ldsm_x4_t(uint32_t* r, uint32_t addr) {
    asm volatile("ldmatrix.sync.aligned.m8n8.x4.trans.shared.b16 {%0,%1,%2,%3}, [%4];"
                 : "=r"(r[0]), "=r"(r[1]), "=r"(r[2]), "=r"(r[3]) : "r"(addr));
}
__device__ __forceinline__ void mma_f16(float* c, const uint32_t* a, const uint32_t* b) {
    asm volatile(
        "mma.sync.aligned.m16n8k16.row.col.f32.f16.f16.f32 "
        "{%0,%1,%2,%3}, {%4,%5,%6,%7}, {%8,%9}, {%0,%1,%2,%3};"
        : "+f"(c[0]), "+f"(c[1]), "+f"(c[2]), "+f"(c[3])
        : "r"(a[0]), "r"(a[1]), "r"(a[2]), "r"(a[3]), "r"(b[0]), "r"(b[1]));
}
__device__ __forceinline__ void mma_f16_b2(float* c, const uint32_t* a,
                                           uint32_t b0, uint32_t b1) {
    uint32_t b[2] = {b0, b1};
    mma_f16(c, a, b);
}
__device__ __forceinline__ void cp_async16(uint32_t dst, const void* src) {
    asm volatile("cp.async.cg.shared.global [%0], [%1], 16;"
                 :: "r"(dst), "l"(src));
}
__device__ __forceinline__ void cp_commit() {
    asm volatile("cp.async.commit_group;" ::: "memory");
}
template <int N> __device__ __forceinline__ void cp_wait() {
    asm volatile("cp.async.wait_group %0;" :: "n"(N) : "memory");
}
__device__ __forceinline__ uint32_t pack2h(float a, float b) {
    __half2 t = __floats2half2_rn(a, b);
    return *(uint32_t*)&t;
}

// ---------------------------------------------------------------------------
// Merged fp32 -> fp16 convert for all 5 tensors.
// ---------------------------------------------------------------------------
__global__ void convert_all_kernel(
    const float* __restrict__ hidden, __half* __restrict__ h_h,
    const float* __restrict__ q_w, __half* __restrict__ qw_h,
    const float* __restrict__ k_w, __half* __restrict__ kw_h,
    const float* __restrict__ v_w, __half* __restrict__ vw_h,
    const float* __restrict__ o_w, __half* __restrict__ ow_h)
{
    int blk = blockIdx.x;
    const float* x; __half* y; int base;
    if (blk < 2048)      { x = hidden; y = h_h;  base = blk; }
    else if (blk < 3072) { x = q_w;    y = qw_h; base = blk - 2048; }
    else if (blk < 3328) { x = k_w;    y = kw_h; base = blk - 3072; }
    else if (blk < 3584) { x = v_w;    y = vw_h; base = blk - 3328; }
    else                 { x = o_w;    y = ow_h; base = blk - 3584; }
    long i = ((long)base * 256 + threadIdx.x) << 4;
    float4 a = *(const float4*)(x + i);
    float4 b = *(const float4*)(x + i + 4);
    float4 c = *(const float4*)(x + i + 8);
    float4 d = *(const float4*)(x + i + 12);
    uint4 u0, u1;
    u0.x = pack2h(a.x, a.y); u0.y = pack2h(a.z, a.w);
    u0.z = pack2h(b.x, b.y); u0.w = pack2h(b.z, b.w);
    u1.x = pack2h(c.x, c.y); u1.y = pack2h(c.z, c.w);
    u1.z = pack2h(d.x, d.y); u1.w = pack2h(d.z, d.w);
    *(uint4*)(y + i) = u0;
    *(uint4*)(y + i + 8) = u1;
}

// ---------------------------------------------------------------------------
// Pipelined 1-term fp16 GEMM core (R14 champion config). Block tile 128x128,
// 256 threads (8 warps, 4x2), warp tile 32x64. BK=64, 3-stage cp.async,
// cp_wait<1>, ONE __syncthreads per K-tile.
// Stage layout: A [0,18432), B [18432,36864). Stage stride 36864.
// ---------------------------------------------------------------------------
#define SSTR 72
#define MAT_BYTES 18432
#define STG_BYTES 36864
#define NSTG 3
#define GSMEM_BYTES (NSTG * STG_BYTES)   // 110592

struct GemmAcc { float a[2][8][4]; };

__device__ __forceinline__ void gemm_stage_load(
    uint32_t sdst, const __half* Ah, const __half* Bh,
    int row0, int col0, int K, int kof, int tid)
{
#pragma unroll
    for (int j = 0; j < 4; j++) {
        int i = tid + j * 256;
        int r = i >> 3, c = (i & 7) * 8;
        uint32_t so = (uint32_t)(r * SSTR + c) * 2;
        cp_async16(sdst + so,             Ah + (long)(row0 + r) * K + kof + c);
        cp_async16(sdst + MAT_BYTES + so, Bh + (long)(col0 + r) * K + kof + c);
    }
}

__device__ __forceinline__ void gemm_core(
    char* smem, const __half* Ah, const __half* Bh,
    int row0, int col0, int K, int tid, int wm, int wn, GemmAcc& A)
{
#pragma unroll
    for (int mt = 0; mt < 2; mt++)
#pragma unroll
        for (int nt = 0; nt < 8; nt++)
#pragma unroll
            for (int j = 0; j < 4; j++) A.a[mt][nt][j] = 0.0f;

    const int lane = tid & 31;
    const uint32_t sb = smem_u32(smem);
    const int x4_r = (lane & 7) + ((lane >> 3) & 1) * 8;
    const int x4_c = (lane >> 4) * 8;

    const int niter = K / 64;

    // prologue: fill 2 stages (commit each; uniform group counting)
#pragma unroll
    for (int s = 0; s < NSTG - 1; s++) {
        if (s < niter)
            gemm_stage_load(sb + (uint32_t)s * STG_BYTES, Ah, Bh,
                            row0, col0, K, s * 64, tid);
        cp_commit();
    }

    int stg_cur = 0;
    for (int kt = 0; kt < niter; kt++) {
        cp_wait<1>();      // group kt complete (committed at iter kt-2)
        __syncthreads();   // stage (kt+2)%3 readers (iter kt-1) done

        int stg_nxt = stg_cur + 2;
        if (stg_nxt >= NSTG) stg_nxt -= NSTG;
        if (kt + 2 < niter)
            gemm_stage_load(sb + (uint32_t)stg_nxt * STG_BYTES, Ah, Bh,
                            row0, col0, K, (kt + 2) * 64, tid);
        cp_commit();

        const uint32_t aA = sb + (uint32_t)stg_cur * STG_BYTES;
        const uint32_t aB = aA + MAT_BYTES;
#pragma unroll
        for (int ks = 0; ks < 4; ks++) {
            uint32_t ah[2][4];
#pragma unroll
            for (int mt = 0; mt < 2; mt++) {
                uint32_t off = (uint32_t)((wm + mt * 16 + x4_r) * SSTR + ks * 16 + x4_c) * 2;
                ldsm_x4(ah[mt], aA + off);
            }
#pragma unroll
            for (int nt2 = 0; nt2 < 4; nt2++) {
                uint32_t boff = (uint32_t)((wn + nt2 * 16 + x4_r) * SSTR + ks * 16 + x4_c) * 2;
                uint32_t bb[4];
                ldsm_x4(bb, aB + boff);
#pragma unroll
                for (int mt = 0; mt < 2; mt++) {
                    mma_f16_b2(A.a[mt][2 * nt2],     ah[mt], bb[0], bb[2]);
                    mma_f16_b2(A.a[mt][2 * nt2 + 1], ah[mt], bb[1], bb[3]);
                }
            }
        }
        if (++stg_cur == NSTG) stg_cur = 0;
    }
    // NOTE: no trailing sync — epilogues / next tile must sync before smem reuse.
}

// ---------------------------------------------------------------------------
// Fused QKV projection, PERSISTENT: grid = 296 CTAs over 768 tiles.
// Tile t: bx = t>>5 (weight panel), by = t&31 (row block).
// ---------------------------------------------------------------------------
__global__ __launch_bounds__(256, 2) void qkv_gemm_kernel(
    const __half* __restrict__ Ah,
    const __half* __restrict__ QWh, const __half* __restrict__ KWh,
    const __half* __restrict__ VWh,
    const float* __restrict__ q_b, const float* __restrict__ k_b,
    const float* __restrict__ v_b,
    __half* __restrict__ Qo, __half* __restrict__ Ko, __half* __restrict__ Vo,
    const float* __restrict__ cosp, const float* __restrict__ sinp)
{
    extern __shared__ __align__(16) char smem[];

    const int tid  = threadIdx.x;
    const int wid  = tid >> 5;
    const int lane = tid & 31;
    const int wm   = (wid >> 1) * 32;
    const int wn   = (wid & 1) * 64;

    for (int t = blockIdx.x; t < 768; t += NPERSIST) {
        __syncthreads();   // previous tile's smem readers done before prologue
        const int bx = t >> 5;
        const int row0 = (t & 31) * 128;

        const __half* Bh;
        const float* bias;
        __half* Chi;
        int N, col0, mode;
        float scale;
        if (bx < 16) {
            Bh = QWh; bias = q_b; Chi = Qo;
            N = NH * HD; col0 = bx * 128; mode = 1; scale = SCALE_F;
        } else if (bx < 20) {
            Bh = KWh; bias = k_b; Chi = Ko;
            N = NKV * HD; col0 = (bx - 16) * 128; mode = 1; scale = 1.0f;
        } else {
            Bh = VWh; bias = v_b; Chi = Vo;
            N = NKV * HD; col0 = (bx - 20) * 128; mode = 2; scale = 1.0f;
        }

        GemmAcc A;
        gemm_core(smem, Ah, Bh, row0, col0, HH, tid, wm, wn, A);

        if (mode == 2) {
            const int em = row0 + wm + (lane >> 2);
            const int enl = wn + (lane & 3) * 2;
#pragma unroll
            for (int mt = 0; mt < 2; mt++) {
#pragma unroll
                for (int nt = 0; nt < 8; nt++) {
                    int n = col0 + enl + nt * 8;
                    float b0 = bias[n], b1 = bias[n + 1];
                    long o0 = (long)(em + mt * 16) * N + n;
                    long o1 = (long)(em + mt * 16 + 8) * N + n;
                    *(uint32_t*)&Chi[o0] = pack2h(A.a[mt][nt][0] + b0, A.a[mt][nt][1] + b1);
                    *(uint32_t*)&Chi[o1] = pack2h(A.a[mt][nt][2] + b0, A.a[mt][nt][3] + b1);
                }
            }
        } else {
            float* buf = (float*)smem;   // 64 x 132 fp32 = 33792 B (< 110592)
            const int r0l = lane >> 2;
            const int c0l = (lane & 3) * 2;
#pragma unroll
            for (int hf = 0; hf < 2; hf++) {
                __syncthreads();   // covers mainloop exit / prior write pass
                int slotA = (wid >> 1) * 16 + r0l;
#pragma unroll
                for (int nt = 0; nt < 8; nt++) {
                    int cc2 = wn + nt * 8 + c0l;
                    float b0 = bias[col0 + cc2];
                    float b1 = bias[col0 + cc2 + 1];
                    buf[slotA * 132 + cc2]           = A.a[hf][nt][0] + b0;
                    buf[slotA * 132 + cc2 + 1]       = A.a[hf][nt][1] + b1;
                    buf[(slotA + 8) * 132 + cc2]     = A.a[hf][nt][2] + b0;
                    buf[(slotA + 8) * 132 + cc2 + 1] = A.a[hf][nt][3] + b1;
                }
                __syncthreads();
                for (int i = tid; i < 4096; i += 256) {
                    int slot = i >> 6, d = i & 63;
                    int grow = row0 + (slot >> 4) * 32 + hf * 16 + (slot & 15);
                    float x1 = buf[slot * 132 + d];
                    float x2 = buf[slot * 132 + d + 64];
                    long cb = (long)grow * HD;
                    float c1 = cosp[cb + d],      s1 = sinp[cb + d];
                    float c2 = cosp[cb + d + 64], s2 = sinp[cb + d + 64];
                    float y1 = (x1 * c1 - x2 * s1) * scale;
                    float y2 = (x2 * c2 + x1 * s2) * scale;
                    long o1 = (long)grow * N + col0 + d;
                    Chi[o1]      = __float2half_rn(y1);
                    Chi[o1 + 64] = __float2half_rn(y2);
                }
            }
        }
    }
}

// ---------------------------------------------------------------------------
// Output projection, PERSISTENT: grid = 296 CTAs over 512 tiles.
// ---------------------------------------------------------------------------
__global__ __launch_bounds__(256, 2) void o_gemm_kernel(
    const __half* __restrict__ Ah, const __half* __restrict__ Bh,
    float* __restrict__ Cf, int M, int N, int K)
{
    extern __shared__ __align__(16) char smem[];
    const int tid  = threadIdx.x;
    const int wid  = tid >> 5;
    const int lane = tid & 31;
    const int wm   = (wid >> 1) * 32;
    const int wn   = (wid & 1) * 64;

    for (int t = blockIdx.x; t < 512; t += NPERSIST) {
        __syncthreads();   // previous tile's smem readers done before prologue
        const int col0 = (t >> 5) * 128;
        const int row0 = (t & 31) * 128;

        GemmAcc A;
        gemm_core(smem, Ah, Bh, row0, col0, K, tid, wm, wn, A);

        const int em = row0 + wm + (lane >> 2);
        const int en = col0 + wn + (lane & 3) * 2;
#pragma unroll
        for (int mt = 0; mt < 2; mt++) {
#pragma unroll
            for (int nt = 0; nt < 8; nt++) {
                int n = en + nt * 8;
                float2 v0, v1;
                v0.x = A.a[mt][nt][0]; v0.y = A.a[mt][nt][1];
                v1.x = A.a[mt][nt][2]; v1.y = A.a[mt][nt][3];
                *(float2*)&Cf[(long)(em + mt * 16) * N + n] = v0;
                *(float2*)&Cf[(long)(em + mt * 16 + 8) * N + n] = v1;
            }
        }
    }
}

// ---------------------------------------------------------------------------
// FA2-style flash attention (unchanged — R10/R11 WIN config).
// smem map: Q [0,34816) | st0 K [34816,52224) V [52224,69632)
//           | st1 K [69632,87040) V [87040,104448). Stage stride 34816.
// ---------------------------------------------------------------------------
#define FQSTR 136
#define FOQ 0u
#define FOK 34816u
#define FKVB 34816u
#define FOV 52224u
#define FSM_BYTES 104448u

__global__ __launch_bounds__(256) void flash_mma_kernel(
    const __half* __restrict__ Qh, const __half* __restrict__ Kh,
    const __half* __restrict__ Vh, __half* __restrict__ AOh)
{
    extern __shared__ char fsm2[];
    const uint32_t sb = smem_u32(fsm2);
    const uint32_t aQ = sb + FOQ;

    const int it = (int)gridDim.x - 1 - (int)blockIdx.x;
    const int h  = blockIdx.y;
    const int b  = blockIdx.z;
    const int g  = h / NREP;
    const int tid  = threadIdx.x;
    const int wid  = tid >> 5;
    const int lane = tid & 31;
    const int wq   = wid * 16;
    const int i0 = it * 128;
    const int m0 = b * SS + i0;

    for (int i = tid; i < 2048; i += 256) {
        int r = i >> 4, c = (i & 15) * 8;
        long gi = (long)(m0 + r) * (NH * HD) + h * HD + c;
        *(uint4*)(fsm2 + FOQ + (r * FQSTR + c) * 2) = *(const uint4*)&Qh[gi];
    }

    const int ntiles = 2 * it + 2;

    {
        uint32_t kd = sb + FOK, vd = sb + FOV;
        for (int i = tid; i < 1024; i += 256) {
            int r = i >> 4, c = (i & 15) * 8;
            long gi = (long)(b * SS + r) * (NKV * HD) + g * HD + c;
            cp_async16(kd + (r * FQSTR + c) * 2, Kh + gi);
            cp_async16(vd + (r * FQSTR + c) * 2, Vh + gi);
        }
        cp_commit();
    }

    float out[16][4];
#pragma unroll
    for (int nt = 0; nt < 16; nt++)
#pragma unroll
        for (int j = 0; j < 4; j++) out[nt][j] = 0.0f;
    float m0r = -1e30f, m1r = -1e30f, l0 = 0.0f, l1 = 0.0f;

    const int r0    = lane >> 2;
    const int qcol2 = (lane & 3) * 2;
    const int x4_r = (lane & 7) + ((lane >> 3) & 1) * 8;
    const int x4_c = (lane >> 4) * 8;

    for (int jt = 0; jt < ntiles; jt++) {
        const int j0 = jt * 64;
        const uint32_t aK = sb + FOK + (uint32_t)(jt & 1) * FKVB;
        const uint32_t aV = sb + FOV + (uint32_t)(jt & 1) * FKVB;

        cp_wait<0>();
        __syncthreads();

        if (jt + 1 < ntiles) {
            uint32_t kd = sb + FOK + (uint32_t)((jt + 1) & 1) * FKVB;
            uint32_t vd = sb + FOV + (uint32_t)((jt + 1) & 1) * FKVB;
            int jn = (jt + 1) * 64;
            for (int i = tid; i < 1024; i += 256) {
                int r = i >> 4, c = (i & 15) * 8;
                long gi = (long)(b * SS + jn + r) * (NKV * HD) + g * HD + c;
                cp_async16(kd + (r * FQSTR + c) * 2, Kh + gi);
                cp_async16(vd + (r * FQSTR + c) * 2, Vh + gi);
            }
            cp_commit();
        }

        float sc[8][4];
#pragma unroll
        for (int nt = 0; nt < 8; nt++)
#pragma unroll
            for (int j = 0; j < 4; j++) sc[nt][j] = 0.0f;

#pragma unroll
        for (int kg = 0; kg < 8; kg++) {
            uint32_t qh[4];
            ldsm_x4(qh, aQ + (uint32_t)((wq + x4_r) * FQSTR + kg * 16 + x4_c) * 2);
#pragma unroll
            for (int nt2 = 0; nt2 < 4; nt2++) {
                uint32_t kb[4];
                ldsm_x4(kb, aK + (uint32_t)((nt2 * 16 + x4_r) * FQSTR + kg * 16 + x4_c) * 2);
                mma_f16_b2(sc[2 * nt2],     qh, kb[0], kb[2]);
                mma_f16_b2(sc[2 * nt2 + 1], qh, kb[1], kb[3]);
            }
        }

        if (j0 + 63 > i0 + wq) {
#pragma unroll
            for (int nt = 0; nt < 8; nt++) {
                int colb = j0 + nt * 8 + qcol2;
                int rowa = i0 + wq + r0;
#pragma unroll
                for (int j = 0; j < 4; j++) {
                    int col = colb + (j & 1);
                    int row = rowa + (j >= 2 ? 8 : 0);
                    if (col > row) sc[nt][j] = -1e30f;
                }
            }
        }

        float mx0 = -1e30f, mx1 = -1e30f;
#pragma unroll
        for (int nt = 0; nt < 8; nt++) {
            mx0 = fmaxf(mx0, fmaxf(sc[nt][0], sc[nt][1]));
            mx1 = fmaxf(mx1, fmaxf(sc[nt][2], sc[nt][3]));
        }
        mx0 = fmaxf(mx0, __shfl_xor_sync(0xffffffffu, mx0, 1));
        mx0 = fmaxf(mx0, __shfl_xor_sync(0xffffffffu, mx0, 2));
        mx1 = fmaxf(mx1, __shfl_xor_sync(0xffffffffu, mx1, 1));
        mx1 = fmaxf(mx1, __shfl_xor_sync(0xffffffffu, mx1, 2));

        float mn0 = fmaxf(m0r, mx0);
        float mn1 = fmaxf(m1r, mx1);
        float al0 = __expf(m0r - mn0);
        float al1 = __expf(m1r - mn1);
        m0r = mn0; m1r = mn1;

        float s0 = 0.0f, s1 = 0.0f;
#pragma unroll
        for (int nt = 0; nt < 8; nt++) {
            sc[nt][0] = __expf(sc[nt][0] - mn0);
            sc[nt][1] = __expf(sc[nt][1] - mn0);
            sc[nt][2] = __expf(sc[nt][2] - mn1);
            sc[nt][3] = __expf(sc[nt][3] - mn1);
            s0 += sc[nt][0] + sc[nt][1];
            s1 += sc[nt][2] + sc[nt][3];
        }
        s0 += __shfl_xor_sync(0xffffffffu, s0, 1);
        s0 += __shfl_xor_sync(0xffffffffu, s0, 2);
        s1 += __shfl_xor_sync(0xffffffffu, s1, 1);
        s1 += __shfl_xor_sync(0xffffffffu, s1, 2);
        l0 = l0 * al0 + s0;
        l1 = l1 * al1 + s1;

#pragma unroll
        for (int nt = 0; nt < 16; nt++) {
            out[nt][0] *= al0; out[nt][1] *= al0;
            out[nt][2] *= al1; out[nt][3] *= al1;
        }

#pragma unroll
        for (int kg = 0; kg < 4; kg++) {
            uint32_t pa[4];
            pa[0] = pack2h(sc[2 * kg][0],     sc[2 * kg][1]);
            pa[1] = pack2h(sc[2 * kg][2],     sc[2 * kg][3]);
            pa[2] = pack2h(sc[2 * kg + 1][0], sc[2 * kg + 1][1]);
            pa[3] = pack2h(sc[2 * kg + 1][2], sc[2 * kg + 1][3]);
#pragma unroll
            for (int ntp = 0; ntp < 8; ntp++) {
                uint32_t vh4[4];
                ldsm_x4_t(vh4, aV + (uint32_t)((kg * 16 + x4_r) * FQSTR + ntp * 16 + x4_c) * 2);
                mma_f16(out[2 * ntp],     pa, &vh4[0]);
                mma_f16(out[2 * ntp + 1], pa, &vh4[2]);
            }
        }
    }

    float inv0 = 1.0f / l0;
    float inv1 = 1.0f / l1;
#pragma unroll
    for (int nt = 0; nt < 16; nt++) {
        int col = nt * 8 + qcol2;
        long ra = (long)(m0 + wq + r0) * (NH * HD) + h * HD + col;
        long rb = (long)(m0 + wq + r0 + 8) * (NH * HD) + h * HD + col;
        *(uint32_t*)&AOh[ra] = pack2h(out[nt][0] * inv0, out[nt][1] * inv0);
        *(uint32_t*)&AOh[rb] = pack2h(out[nt][2] * inv1, out[nt][3] * inv1);
    }
}

// ---------------------------------------------------------------------------
// Launcher
// ---------------------------------------------------------------------------
extern "C" void kernel_launch(void* const* d_in, const int* in_sizes, int n_in,
                              void* d_out, int out_size)
{
    const float* hidden = (const float*)d_in[0];
    const float* cosp   = (const float*)d_in[1];
    const float* sinp   = (const float*)d_in[2];
    const float* q_w = (const float*)d_in[4];
    const float* q_b = (const float*)d_in[5];
    const float* k_w = (const float*)d_in[6];
    const float* k_b = (const float*)d_in[7];
    const float* v_w = (const float*)d_in[8];
    const float* v_b = (const float*)d_in[9];
    const float* o_w = (const float*)d_in[10];
    float* out = (float*)d_out;

    __half *h_h, *qw_h, *kw_h, *vw_h, *ow_h, *qh, *kh, *vh, *ao_h;
    cudaGetSymbolAddress((void**)&h_h, g_h_h);
    cudaGetSymbolAddress((void**)&qw_h, g_qw_h);
    cudaGetSymbolAddress((void**)&kw_h, g_kw_h);
    cudaGetSymbolAddress((void**)&vw_h, g_vw_h);
    cudaGetSymbolAddress((void**)&ow_h, g_ow_h);
    cudaGetSymbolAddress((void**)&qh, g_qh);
    cudaGetSymbolAddress((void**)&kh, g_kh);
    cudaGetSymbolAddress((void**)&vh, g_vh);
    cudaGetSymbolAddress((void**)&ao_h, g_ao_h);

    // One merged convert launch
    convert_all_kernel<<<4608, 256>>>(hidden, h_h, q_w, qw_h, k_w, kw_h,
                                      v_w, vw_h, o_w, ow_h);

    // Fused QKV projection (persistent)
    cudaFuncSetAttribute(qkv_gemm_kernel,
                         cudaFuncAttributeMaxDynamicSharedMemorySize, GSMEM_BYTES);
    qkv_gemm_kernel<<<NPERSIST, 256, GSMEM_BYTES>>>(
        h_h, qw_h, kw_h, vw_h, q_b, k_b, v_b, qh, kh, vh, cosp, sinp);

    // Flash attention
    cudaFuncSetAttribute(flash_mma_kernel,
                         cudaFuncAttributeMaxDynamicSharedMemorySize, FSM_BYTES);
    flash_mma_kernel<<<dim3(SS / 128, NH, BB), 256, FSM_BYTES>>>(
        qh, kh, vh, ao_h);

    // Output projection (persistent)
    cudaFuncSetAttribute(o_gemm_kernel,
                         cudaFuncAttributeMaxDynamicSharedMemorySize, GSMEM_BYTES);
    o_gemm_kernel<<<NPERSIST, 256, GSMEM_BYTES>>>(
        ao_h, ow_h, out, M_TOK, HH, NH * HD);
}

// round 17
// speedup vs baseline: 1.0320x; 1.0140x over previous
#include <cuda_runtime.h>
#include <cuda_fp16.h>
#include <math.h>
#include <stdint.h>

// Problem constants
#define BB 2
#define SS 2048
#define HH 2048
#define NH 16
#define NKV 4
#define HD 128
#define NREP (NH / NKV)
#define M_TOK (BB * SS)
#define SCALE_F 0.08838834764831845f

// ---------------------------------------------------------------------------
// Scratch (fp16 hi-only)
// ---------------------------------------------------------------------------
__device__ __half g_h_h[M_TOK * HH];
__device__ __half g_qw_h[NH * HD * HH];
__device__ __half g_kw_h[NKV * HD * HH];
__device__ __half g_vw_h[NKV * HD * HH];
__device__ __half g_ow_h[HH * NH * HD];
__device__ __half g_qh[M_TOK * NH * HD];
__device__ __half g_kh[M_TOK * NKV * HD];
__device__ __half g_vh[M_TOK * NKV * HD];
__device__ __half g_ao_h[M_TOK * NH * HD];

// ---------------------------------------------------------------------------
// Helpers
// ---------------------------------------------------------------------------
__device__ __forceinline__ uint32_t smem_u32(const void* p) {
    uint32_t a;
    asm("{ .reg .u64 t; cvta.to.shared.u64 t, %1; cvt.u32.u64 %0, t; }"
        : "=r"(a) : "l"(p));
    return a;
}
__device__ __forceinline__ void ldsm_x4(uint32_t* r, uint32_t addr) {
    asm volatile("ldmatrix.sync.aligned.m8n8.x4.shared.b16 {%0,%1,%2,%3}, [%4];"
                 : "=r"(r[0]), "=r"(r[1]), "=r"(r[2]), "=r"(r[3]) : "r"(addr));
}
__device__ __forceinline__ void ldsm_x4_t(uint32_t* r, uint32_t addr) {
    asm volatile("ldmatrix.sync.aligned.m8n8.x4.trans.shared.b16 {%0,%1,%2,%3}, [%4];"
                 : "=r"(r[0]), "=r"(r[1]), "=r"(r[2]), "=r"(r[3]) : "r"(addr));
}
__device__ __forceinline__ void mma_f16(float* c, const uint32_t* a, const uint32_t* b) {
    asm volatile(
        "mma.sync.aligned.m16n8k16.row.col.f32.f16.f16.f32 "
        "{%0,%1,%2,%3}, {%4,%5,%6,%7}, {%8,%9}, {%0,%1,%2,%3};"
        : "+f"(c[0]), "+f"(c[1]), "+f"(c[2]), "+f"(c[3])
        : "r"(a[0]), "r"(a[1]), "r"(a[2]), "r"(a[3]), "r"(b[0]), "r"(b[1]));
}
__device__ __forceinline__ void mma_f16_b2(float* c, const uint32_t* a,
                                           uint32_t b0, uint32_t b1) {
    uint32_t b[2] = {b0, b1};
    mma_f16(c, a, b);
}
__device__ __forceinline__ void cp_async16(uint32_t dst, const void* src) {
    asm volatile("cp.async.cg.shared.global [%0], [%1], 16;"
                 :: "r"(dst), "l"(src));
}
__device__ __forceinline__ void cp_commit() {
    asm volatile("cp.async.commit_group;" ::: "memory");
}
template <int N> __device__ __forceinline__ void cp_wait() {
    asm volatile("cp.async.wait_group %0;" :: "n"(N) : "memory");
}
__device__ __forceinline__ uint32_t pack2h(float a, float b) {
    __half2 t = __floats2half2_rn(a, b);
    return *(uint32_t*)&t;
}

// ---------------------------------------------------------------------------
// Merged fp32 -> fp16 convert for all 5 tensors.
// ---------------------------------------------------------------------------
__global__ void convert_all_kernel(
    const float* __restrict__ hidden, __half* __restrict__ h_h,
    const float* __restrict__ q_w, __half* __restrict__ qw_h,
    const float* __restrict__ k_w, __half* __restrict__ kw_h,
    const float* __restrict__ v_w, __half* __restrict__ vw_h,
    const float* __restrict__ o_w, __half* __restrict__ ow_h)
{
    int blk = blockIdx.x;
    const float* x; __half* y; int base;
    if (blk < 2048)      { x = hidden; y = h_h;  base = blk; }
    else if (blk < 3072) { x = q_w;    y = qw_h; base = blk - 2048; }
    else if (blk < 3328) { x = k_w;    y = kw_h; base = blk - 3072; }
    else if (blk < 3584) { x = v_w;    y = vw_h; base = blk - 3328; }
    else                 { x = o_w;    y = ow_h; base = blk - 3584; }
    long i = ((long)base * 256 + threadIdx.x) << 4;
    float4 a = *(const float4*)(x + i);
    float4 b = *(const float4*)(x + i + 4);
    float4 c = *(const float4*)(x + i + 8);
    float4 d = *(const float4*)(x + i + 12);
    uint4 u0, u1;
    u0.x = pack2h(a.x, a.y); u0.y = pack2h(a.z, a.w);
    u0.z = pack2h(b.x, b.y); u0.w = pack2h(b.z, b.w);
    u1.x = pack2h(c.x, c.y); u1.y = pack2h(c.z, c.w);
    u1.z = pack2h(d.x, d.y); u1.w = pack2h(d.z, d.w);
    *(uint4*)(y + i) = u0;
    *(uint4*)(y + i + 8) = u1;
}

// ---------------------------------------------------------------------------
// Pipelined 1-term fp16 GEMM core (R14 champion). Block tile 128x128,
// 256 threads (8 warps, 4x2), warp tile 32x64. BK=64, 3-stage cp.async,
// cp_wait<1>, ONE __syncthreads per K-tile.
// ---------------------------------------------------------------------------
#define SSTR 72
#define MAT_BYTES 18432
#define STG_BYTES 36864
#define NSTG 3
#define GSMEM_BYTES (NSTG * STG_BYTES)   // 110592

struct GemmAcc { float a[2][8][4]; };

__device__ __forceinline__ void gemm_stage_load(
    uint32_t sdst, const __half* Ah, const __half* Bh,
    int row0, int col0, int K, int kof, int tid)
{
#pragma unroll
    for (int j = 0; j < 4; j++) {
        int i = tid + j * 256;
        int r = i >> 3, c = (i & 7) * 8;
        uint32_t so = (uint32_t)(r * SSTR + c) * 2;
        cp_async16(sdst + so,             Ah + (long)(row0 + r) * K + kof + c);
        cp_async16(sdst + MAT_BYTES + so, Bh + (long)(col0 + r) * K + kof + c);
    }
}

__device__ __forceinline__ void gemm_core(
    char* smem, const __half* Ah, const __half* Bh,
    int row0, int col0, int K, int tid, int wm, int wn, GemmAcc& A)
{
#pragma unroll
    for (int mt = 0; mt < 2; mt++)
#pragma unroll
        for (int nt = 0; nt < 8; nt++)
#pragma unroll
            for (int j = 0; j < 4; j++) A.a[mt][nt][j] = 0.0f;

    const int lane = tid & 31;
    const uint32_t sb = smem_u32(smem);
    const int x4_r = (lane & 7) + ((lane >> 3) & 1) * 8;
    const int x4_c = (lane >> 4) * 8;

    const int niter = K / 64;

#pragma unroll
    for (int s = 0; s < NSTG - 1; s++) {
        if (s < niter)
            gemm_stage_load(sb + (uint32_t)s * STG_BYTES, Ah, Bh,
                            row0, col0, K, s * 64, tid);
        cp_commit();
    }

    int stg_cur = 0;
    for (int kt = 0; kt < niter; kt++) {
        cp_wait<1>();
        __syncthreads();

        int stg_nxt = stg_cur + 2;
        if (stg_nxt >= NSTG) stg_nxt -= NSTG;
        if (kt + 2 < niter)
            gemm_stage_load(sb + (uint32_t)stg_nxt * STG_BYTES, Ah, Bh,
                            row0, col0, K, (kt + 2) * 64, tid);
        cp_commit();

        const uint32_t aA = sb + (uint32_t)stg_cur * STG_BYTES;
        const uint32_t aB = aA + MAT_BYTES;
#pragma unroll
        for (int ks = 0; ks < 4; ks++) {
            uint32_t ah[2][4];
#pragma unroll
            for (int mt = 0; mt < 2; mt++) {
                uint32_t off = (uint32_t)((wm + mt * 16 + x4_r) * SSTR + ks * 16 + x4_c) * 2;
                ldsm_x4(ah[mt], aA + off);
            }
#pragma unroll
            for (int nt2 = 0; nt2 < 4; nt2++) {
                uint32_t boff = (uint32_t)((wn + nt2 * 16 + x4_r) * SSTR + ks * 16 + x4_c) * 2;
                uint32_t bb[4];
                ldsm_x4(bb, aB + boff);
#pragma unroll
                for (int mt = 0; mt < 2; mt++) {
                    mma_f16_b2(A.a[mt][2 * nt2],     ah[mt], bb[0], bb[2]);
                    mma_f16_b2(A.a[mt][2 * nt2 + 1], ah[mt], bb[1], bb[3]);
                }
            }
        }
        if (++stg_cur == NSTG) stg_cur = 0;
    }
}

// ---------------------------------------------------------------------------
// Fused QKV projection (R14 config). grid = (24, 32).
// ---------------------------------------------------------------------------
__global__ __launch_bounds__(256, 2) void qkv_gemm_kernel(
    const __half* __restrict__ Ah,
    const __half* __restrict__ QWh, const __half* __restrict__ KWh,
    const __half* __restrict__ VWh,
    const float* __restrict__ q_b, const float* __restrict__ k_b,
    const float* __restrict__ v_b,
    __half* __restrict__ Qo, __half* __restrict__ Ko, __half* __restrict__ Vo,
    const float* __restrict__ cosp, const float* __restrict__ sinp)
{
    extern __shared__ __align__(16) char smem[];

    const int bx = blockIdx.x;
    const __half* Bh;
    const float* bias;
    __half* Chi;
    int N, col0, mode;
    float scale;
    if (bx < 16) {
        Bh = QWh; bias = q_b; Chi = Qo;
        N = NH * HD; col0 = bx * 128; mode = 1; scale = SCALE_F;
    } else if (bx < 20) {
        Bh = KWh; bias = k_b; Chi = Ko;
        N = NKV * HD; col0 = (bx - 16) * 128; mode = 1; scale = 1.0f;
    } else {
        Bh = VWh; bias = v_b; Chi = Vo;
        N = NKV * HD; col0 = (bx - 20) * 128; mode = 2; scale = 1.0f;
    }

    const int tid  = threadIdx.x;
    const int wid  = tid >> 5;
    const int lane = tid & 31;
    const int wm   = (wid >> 1) * 32;
    const int wn   = (wid & 1) * 64;
    const int row0 = blockIdx.y * 128;

    GemmAcc A;
    gemm_core(smem, Ah, Bh, row0, col0, HH, tid, wm, wn, A);

    if (mode == 2) {
        const int em = row0 + wm + (lane >> 2);
        const int enl = wn + (lane & 3) * 2;
#pragma unroll
        for (int mt = 0; mt < 2; mt++) {
#pragma unroll
            for (int nt = 0; nt < 8; nt++) {
                int n = col0 + enl + nt * 8;
                float b0 = bias[n], b1 = bias[n + 1];
                long o0 = (long)(em + mt * 16) * N + n;
                long o1 = (long)(em + mt * 16 + 8) * N + n;
                *(uint32_t*)&Chi[o0] = pack2h(A.a[mt][nt][0] + b0, A.a[mt][nt][1] + b1);
                *(uint32_t*)&Chi[o1] = pack2h(A.a[mt][nt][2] + b0, A.a[mt][nt][3] + b1);
            }
        }
    } else {
        float* buf = (float*)smem;
        const int r0l = lane >> 2;
        const int c0l = (lane & 3) * 2;
#pragma unroll
        for (int hf = 0; hf < 2; hf++) {
            __syncthreads();
            int slotA = (wid >> 1) * 16 + r0l;
#pragma unroll
            for (int nt = 0; nt < 8; nt++) {
                int cc2 = wn + nt * 8 + c0l;
                float b0 = bias[col0 + cc2];
                float b1 = bias[col0 + cc2 + 1];
                buf[slotA * 132 + cc2]           = A.a[hf][nt][0] + b0;
                buf[slotA * 132 + cc2 + 1]       = A.a[hf][nt][1] + b1;
                buf[(slotA + 8) * 132 + cc2]     = A.a[hf][nt][2] + b0;
                buf[(slotA + 8) * 132 + cc2 + 1] = A.a[hf][nt][3] + b1;
            }
            __syncthreads();
            for (int i = tid; i < 4096; i += 256) {
                int slot = i >> 6, d = i & 63;
                int grow = row0 + (slot >> 4) * 32 + hf * 16 + (slot & 15);
                float x1 = buf[slot * 132 + d];
                float x2 = buf[slot * 132 + d + 64];
                long cb = (long)grow * HD;
                float c1 = cosp[cb + d],      s1 = sinp[cb + d];
                float c2 = cosp[cb + d + 64], s2 = sinp[cb + d + 64];
                float y1 = (x1 * c1 - x2 * s1) * scale;
                float y2 = (x2 * c2 + x1 * s2) * scale;
                long o1 = (long)grow * N + col0 + d;
                Chi[o1]      = __float2half_rn(y1);
                Chi[o1 + 64] = __float2half_rn(y2);
            }
        }
    }
}

// ---------------------------------------------------------------------------
// Output projection (R14 config): fp32 out, no bias. grid = (16, 32).
// ---------------------------------------------------------------------------
__global__ __launch_bounds__(256, 2) void o_gemm_kernel(
    const __half* __restrict__ Ah, const __half* __restrict__ Bh,
    float* __restrict__ Cf, int M, int N, int K)
{
    extern __shared__ __align__(16) char smem[];
    const int tid  = threadIdx.x;
    const int wid  = tid >> 5;
    const int lane = tid & 31;
    const int wm   = (wid >> 1) * 32;
    const int wn   = (wid & 1) * 64;
    const int row0 = blockIdx.y * 128;
    const int col0 = blockIdx.x * 128;

    GemmAcc A;
    gemm_core(smem, Ah, Bh, row0, col0, K, tid, wm, wn, A);

    const int em = row0 + wm + (lane >> 2);
    const int en = col0 + wn + (lane & 3) * 2;
#pragma unroll
    for (int mt = 0; mt < 2; mt++) {
#pragma unroll
        for (int nt = 0; nt < 8; nt++) {
            int n = en + nt * 8;
            float2 v0, v1;
            v0.x = A.a[mt][nt][0]; v0.y = A.a[mt][nt][1];
            v1.x = A.a[mt][nt][2]; v1.y = A.a[mt][nt][3];
            *(float2*)&Cf[(long)(em + mt * 16) * N + n] = v0;
            *(float2*)&Cf[(long)(em + mt * 16 + 8) * N + n] = v1;
        }
    }
}

// ---------------------------------------------------------------------------
// PERSISTENT FA2-style flash attention. grid = 148 CTAs over 512 tiles,
// heavy-first static schedule: tile tt -> it = 15 - (tt>>5), hb = tt&31.
// smem map: Q [0,34816) | st0 K [34816,52224) V [52224,69632)
//           | st1 K [69632,87040) V [87040,104448). Stage stride 34816.
// ---------------------------------------------------------------------------
#define FQSTR 136
#define FOQ 0u
#define FOK 34816u
#define FKVB 34816u
#define FOV 52224u
#define FSM_BYTES 104448u
#define FLASH_CTAS 148
#define NTILES_F 512

__global__ __launch_bounds__(256) void flash_mma_kernel(
    const __half* __restrict__ Qh, const __half* __restrict__ Kh,
    const __half* __restrict__ Vh, __half* __restrict__ AOh)
{
    extern __shared__ char fsm2[];
    const uint32_t sb = smem_u32(fsm2);
    const uint32_t aQ = sb + FOQ;

    const int tid  = threadIdx.x;
    const int wid  = tid >> 5;
    const int lane = tid & 31;
    const int wq   = wid * 16;

    const int r0    = lane >> 2;
    const int qcol2 = (lane & 3) * 2;
    const int x4_r = (lane & 7) + ((lane >> 3) & 1) * 8;
    const int x4_c = (lane >> 4) * 8;

    for (int tt = blockIdx.x; tt < NTILES_F; tt += FLASH_CTAS) {
        const int it = 15 - (tt >> 5);     // heavy tiles first
        const int hb = tt & 31;
        const int h  = hb >> 1;
        const int b  = hb & 1;
        const int g  = h / NREP;
        const int i0 = it * 128;
        const int m0 = b * SS + i0;

        __syncthreads();   // prior tile's smem readers done before Q/KV overwrite

        // Load Q tile
        for (int i = tid; i < 2048; i += 256) {
            int r = i >> 4, c = (i & 15) * 8;
            long gi = (long)(m0 + r) * (NH * HD) + h * HD + c;
            *(uint4*)(fsm2 + FOQ + (r * FQSTR + c) * 2) = *(const uint4*)&Qh[gi];
        }

        const int ntiles = 2 * it + 2;

        // prologue: K/V tile 0 into stage 0
        {
            uint32_t kd = sb + FOK, vd = sb + FOV;
            for (int i = tid; i < 1024; i += 256) {
                int r = i >> 4, c = (i & 15) * 8;
                long gi = (long)(b * SS + r) * (NKV * HD) + g * HD + c;
                cp_async16(kd + (r * FQSTR + c) * 2, Kh + gi);
                cp_async16(vd + (r * FQSTR + c) * 2, Vh + gi);
            }
            cp_commit();
        }

        float out[16][4];
#pragma unroll
        for (int nt = 0; nt < 16; nt++)
#pragma unroll
            for (int j = 0; j < 4; j++) out[nt][j] = 0.0f;
        float m0r = -1e30f, m1r = -1e30f, l0 = 0.0f, l1 = 0.0f;

        for (int jt = 0; jt < ntiles; jt++) {
            const int j0 = jt * 64;
            const uint32_t aK = sb + FOK + (uint32_t)(jt & 1) * FKVB;
            const uint32_t aV = sb + FOV + (uint32_t)(jt & 1) * FKVB;

            cp_wait<0>();
            __syncthreads();

            if (jt + 1 < ntiles) {
                uint32_t kd = sb + FOK + (uint32_t)((jt + 1) & 1) * FKVB;
                uint32_t vd = sb + FOV + (uint32_t)((jt + 1) & 1) * FKVB;
                int jn = (jt + 1) * 64;
                for (int i = tid; i < 1024; i += 256) {
                    int r = i >> 4, c = (i & 15) * 8;
                    long gi = (long)(b * SS + jn + r) * (NKV * HD) + g * HD + c;
                    cp_async16(kd + (r * FQSTR + c) * 2, Kh + gi);
                    cp_async16(vd + (r * FQSTR + c) * 2, Vh + gi);
                }
                cp_commit();
            }

            float sc[8][4];
#pragma unroll
            for (int nt = 0; nt < 8; nt++)
#pragma unroll
                for (int j = 0; j < 4; j++) sc[nt][j] = 0.0f;

#pragma unroll
            for (int kg = 0; kg < 8; kg++) {
                uint32_t qh[4];
                ldsm_x4(qh, aQ + (uint32_t)((wq + x4_r) * FQSTR + kg * 16 + x4_c) * 2);
#pragma unroll
                for (int nt2 = 0; nt2 < 4; nt2++) {
                    uint32_t kb[4];
                    ldsm_x4(kb, aK + (uint32_t)((nt2 * 16 + x4_r) * FQSTR + kg * 16 + x4_c) * 2);
                    mma_f16_b2(sc[2 * nt2],     qh, kb[0], kb[2]);
                    mma_f16_b2(sc[2 * nt2 + 1], qh, kb[1], kb[3]);
                }
            }

            if (j0 + 63 > i0 + wq) {
#pragma unroll
                for (int nt = 0; nt < 8; nt++) {
                    int colb = j0 + nt * 8 + qcol2;
                    int rowa = i0 + wq + r0;
#pragma unroll
                    for (int j = 0; j < 4; j++) {
                        int col = colb + (j & 1);
                        int row = rowa + (j >= 2 ? 8 : 0);
                        if (col > row) sc[nt][j] = -1e30f;
                    }
                }
            }

            float mx0 = -1e30f, mx1 = -1e30f;
#pragma unroll
            for (int nt = 0; nt < 8; nt++) {
                mx0 = fmaxf(mx0, fmaxf(sc[nt][0], sc[nt][1]));
                mx1 = fmaxf(mx1, fmaxf(sc[nt][2], sc[nt][3]));
            }
            mx0 = fmaxf(mx0, __shfl_xor_sync(0xffffffffu, mx0, 1));
            mx0 = fmaxf(mx0, __shfl_xor_sync(0xffffffffu, mx0, 2));
            mx1 = fmaxf(mx1, __shfl_xor_sync(0xffffffffu, mx1, 1));
            mx1 = fmaxf(mx1, __shfl_xor_sync(0xffffffffu, mx1, 2));

            float mn0 = fmaxf(m0r, mx0);
            float mn1 = fmaxf(m1r, mx1);
            float al0 = __expf(m0r - mn0);
            float al1 = __expf(m1r - mn1);
            m0r = mn0; m1r = mn1;

            float s0 = 0.0f, s1 = 0.0f;
#pragma unroll
            for (int nt = 0; nt < 8; nt++) {
                sc[nt][0] = __expf(sc[nt][0] - mn0);
                sc[nt][1] = __expf(sc[nt][1] - mn0);
                sc[nt][2] = __expf(sc[nt][2] - mn1);
                sc[nt][3] = __expf(sc[nt][3] - mn1);
                s0 += sc[nt][0] + sc[nt][1];
                s1 += sc[nt][2] + sc[nt][3];
            }
            s0 += __shfl_xor_sync(0xffffffffu, s0, 1);
            s0 += __shfl_xor_sync(0xffffffffu, s0, 2);
            s1 += __shfl_xor_sync(0xffffffffu, s1, 1);
            s1 += __shfl_xor_sync(0xffffffffu, s1, 2);
            l0 = l0 * al0 + s0;
            l1 = l1 * al1 + s1;

#pragma unroll
            for (int nt = 0; nt < 16; nt++) {
                out[nt][0] *= al0; out[nt][1] *= al0;
                out[nt][2] *= al1; out[nt][3] *= al1;
            }

#pragma unroll
            for (int kg = 0; kg < 4; kg++) {
                uint32_t pa[4];
                pa[0] = pack2h(sc[2 * kg][0],     sc[2 * kg][1]);
                pa[1] = pack2h(sc[2 * kg][2],     sc[2 * kg][3]);
                pa[2] = pack2h(sc[2 * kg + 1][0], sc[2 * kg + 1][1]);
                pa[3] = pack2h(sc[2 * kg + 1][2], sc[2 * kg + 1][3]);
#pragma unroll
                for (int ntp = 0; ntp < 8; ntp++) {
                    uint32_t vh4[4];
                    ldsm_x4_t(vh4, aV + (uint32_t)((kg * 16 + x4_r) * FQSTR + ntp * 16 + x4_c) * 2);
                    mma_f16(out[2 * ntp],     pa, &vh4[0]);
                    mma_f16(out[2 * ntp + 1], pa, &vh4[2]);
                }
            }
        }

        float inv0 = 1.0f / l0;
        float inv1 = 1.0f / l1;
#pragma unroll
        for (int nt = 0; nt < 16; nt++) {
            int col = nt * 8 + qcol2;
            long ra = (long)(m0 + wq + r0) * (NH * HD) + h * HD + col;
            long rb = (long)(m0 + wq + r0 + 8) * (NH * HD) + h * HD + col;
            *(uint32_t*)&AOh[ra] = pack2h(out[nt][0] * inv0, out[nt][1] * inv0);
            *(uint32_t*)&AOh[rb] = pack2h(out[nt][2] * inv1, out[nt][3] * inv1);
        }
    }
}

// ---------------------------------------------------------------------------
// Launcher
// ---------------------------------------------------------------------------
extern "C" void kernel_launch(void* const* d_in, const int* in_sizes, int n_in,
                              void* d_out, int out_size)
{
    const float* hidden = (const float*)d_in[0];
    const float* cosp   = (const float*)d_in[1];
    const float* sinp   = (const float*)d_in[2];
    const float* q_w = (const float*)d_in[4];
    const float* q_b = (const float*)d_in[5];
    const float* k_w = (const float*)d_in[6];
    const float* k_b = (const float*)d_in[7];
    const float* v_w = (const float*)d_in[8];
    const float* v_b = (const float*)d_in[9];
    const float* o_w = (const float*)d_in[10];
    float* out = (float*)d_out;

    __half *h_h, *qw_h, *kw_h, *vw_h, *ow_h, *qh, *kh, *vh, *ao_h;
    cudaGetSymbolAddress((void**)&h_h, g_h_h);
    cudaGetSymbolAddress((void**)&qw_h, g_qw_h);
    cudaGetSymbolAddress((void**)&kw_h, g_kw_h);
    cudaGetSymbolAddress((void**)&vw_h, g_vw_h);
    cudaGetSymbolAddress((void**)&ow_h, g_ow_h);
    cudaGetSymbolAddress((void**)&qh, g_qh);
    cudaGetSymbolAddress((void**)&kh, g_kh);
    cudaGetSymbolAddress((void**)&vh, g_vh);
    cudaGetSymbolAddress((void**)&ao_h, g_ao_h);

    // One merged convert launch
    convert_all_kernel<<<4608, 256>>>(hidden, h_h, q_w, qw_h, k_w, kw_h,
                                      v_w, vw_h, o_w, ow_h);

    // Fused QKV projection (R14 config)
    cudaFuncSetAttribute(qkv_gemm_kernel,
                         cudaFuncAttributeMaxDynamicSharedMemorySize, GSMEM_BYTES);
    qkv_gemm_kernel<<<dim3(24, M_TOK / 128), 256, GSMEM_BYTES>>>(
        h_h, qw_h, kw_h, vw_h, q_b, k_b, v_b, qh, kh, vh, cosp, sinp);

    // Flash attention (persistent, heavy-first schedule)
    cudaFuncSetAttribute(flash_mma_kernel,
                         cudaFuncAttributeMaxDynamicSharedMemorySize, FSM_BYTES);
    flash_mma_kernel<<<FLASH_CTAS, 256, FSM_BYTES>>>(qh, kh, vh, ao_h);

    // Output projection (R14 config)
    cudaFuncSetAttribute(o_gemm_kernel,
                         cudaFuncAttributeMaxDynamicSharedMemorySize, GSMEM_BYTES);
    o_gemm_kernel<<<dim3(HH / 128, M_TOK / 128), 256, GSMEM_BYTES>>>(
        ao_h, ow_h, out, M_TOK, HH, NH * HD);
}